// round 3
// baseline (speedup 1.0000x reference)
#include <cuda_runtime.h>

#define D 128
#define MAX_NODES 50000

// Scratch accumulator (allocation-free rule: __device__ global)
__device__ float g_agg[MAX_NODES * D];

// ---------------------------------------------------------------------------
// Kernel 1: zero the accumulator
// ---------------------------------------------------------------------------
__global__ void zero_agg_kernel(int n4) {
    int i = blockIdx.x * blockDim.x + threadIdx.x;
    if (i < n4) {
        ((float4*)g_agg)[i] = make_float4(0.f, 0.f, 0.f, 0.f);
    }
}

// ---------------------------------------------------------------------------
// Kernel 2: edge scatter.  One warp per edge; lane l handles floats [4l, 4l+4).
// feature row read is a fully-coalesced 512B transaction per warp.
// Indices are int32 (harness downcasts the reference's int64).
// ---------------------------------------------------------------------------
__global__ void scatter_kernel(const float* __restrict__ feature,
                               const int* __restrict__ src,
                               const int* __restrict__ dst,
                               const float* __restrict__ w,
                               int E) {
    int t = blockIdx.x * blockDim.x + threadIdx.x;
    int e = t >> 5;
    if (e >= E) return;
    int lane = t & 31;

    int s    = __ldg(&src[e]);
    int d    = __ldg(&dst[e]);
    float we = __ldg(&w[e]);

    float4 v = *(const float4*)(feature + (long long)s * D + lane * 4);
    float* o = g_agg + (long long)d * D + lane * 4;
    atomicAdd(o + 0, v.x * we);
    atomicAdd(o + 1, v.y * we);
    atomicAdd(o + 2, v.z * we);
    atomicAdd(o + 3, v.w * we);
}

// ---------------------------------------------------------------------------
// Kernel 3: out = relu(agg @ W^T + b)
// BM=BN=128, BK=32, 256 threads, 8x8 register microtile per thread.
// smem tiles stored k-major with stride 132 (pad) -> conflict-free.
// ---------------------------------------------------------------------------
#define BK 32
#define SAP 132   // padded row stride for smem tiles

__global__ void gemm_bias_relu_kernel(const float* __restrict__ Wm,   // [128,128]
                                      const float* __restrict__ bias, // [128]
                                      float* __restrict__ out,        // [M,128]
                                      int M) {
    __shared__ float sA[BK * SAP];
    __shared__ float sW[BK * SAP];

    int tid = threadIdx.x;
    int tx = tid & 15;        // col group
    int ty = tid >> 4;        // row group
    int br = blockIdx.x * 128;

    float acc[8][8];
#pragma unroll
    for (int i = 0; i < 8; i++)
#pragma unroll
        for (int j = 0; j < 8; j++) acc[i][j] = 0.f;

    for (int kt = 0; kt < D; kt += BK) {
        // Load tiles: 128 rows x 32 k-cols each; 256 thr x 4 float4 = 4096 elems
#pragma unroll
        for (int it = 0; it < 4; it++) {
            int idx4 = tid + it * 256;       // [0,1024)
            int m  = idx4 >> 3;              // row within tile (0..127)
            int kq = idx4 & 7;               // float4 index within 32 k's
            int k  = kq * 4;

            float4 va = make_float4(0.f, 0.f, 0.f, 0.f);
            if (br + m < M)
                va = *(const float4*)(g_agg + (long long)(br + m) * D + kt + k);
            sA[(k + 0) * SAP + m] = va.x;
            sA[(k + 1) * SAP + m] = va.y;
            sA[(k + 2) * SAP + m] = va.z;
            sA[(k + 3) * SAP + m] = va.w;

            float4 vw = *(const float4*)(Wm + m * D + kt + k);   // W row m = output col m
            sW[(k + 0) * SAP + m] = vw.x;
            sW[(k + 1) * SAP + m] = vw.y;
            sW[(k + 2) * SAP + m] = vw.z;
            sW[(k + 3) * SAP + m] = vw.w;
        }
        __syncthreads();

#pragma unroll
        for (int k = 0; k < BK; k++) {
            float a[8], wr[8];
            *(float4*)(a)      = *(const float4*)&sA[k * SAP + ty * 8];
            *(float4*)(a + 4)  = *(const float4*)&sA[k * SAP + ty * 8 + 4];
            *(float4*)(wr)     = *(const float4*)&sW[k * SAP + tx * 8];
            *(float4*)(wr + 4) = *(const float4*)&sW[k * SAP + tx * 8 + 4];
#pragma unroll
            for (int i = 0; i < 8; i++)
#pragma unroll
                for (int j = 0; j < 8; j++)
                    acc[i][j] += a[i] * wr[j];
        }
        __syncthreads();
    }

    // Epilogue: bias + relu, vectorized stores
    float bv[8];
#pragma unroll
    for (int j = 0; j < 8; j++) bv[j] = bias[tx * 8 + j];

#pragma unroll
    for (int i = 0; i < 8; i++) {
        int m = br + ty * 8 + i;
        if (m < M) {
            float r[8];
#pragma unroll
            for (int j = 0; j < 8; j++) {
                float v = acc[i][j] + bv[j];
                r[j] = v > 0.f ? v : 0.f;
            }
            float* op = out + (long long)m * D + tx * 8;
            *(float4*)(op)     = *(const float4*)(r);
            *(float4*)(op + 4) = *(const float4*)(r + 4);
        }
    }
}

// ---------------------------------------------------------------------------
// Launch
// Inputs (metadata order): feature f32[N*128], src i32[E], dst i32[E],
//                          w f32[E], W f32[128*128], b f32[128]
// Output: f32[N*128]
// ---------------------------------------------------------------------------
extern "C" void kernel_launch(void* const* d_in, const int* in_sizes, int n_in,
                              void* d_out, int out_size) {
    const float* feature = (const float*)d_in[0];
    const int*   src     = (const int*)d_in[1];
    const int*   dst     = (const int*)d_in[2];
    const float* w       = (const float*)d_in[3];
    const float* Wm      = (const float*)d_in[4];
    const float* bias    = (const float*)d_in[5];
    float*       out     = (float*)d_out;

    int M = in_sizes[0] / D;    // number of nodes
    int E = in_sizes[1];        // number of edges

    // 1) zero accumulator
    int n4 = (M * D) / 4;
    zero_agg_kernel<<<(n4 + 255) / 256, 256>>>(n4);

    // 2) edge scatter: one warp per edge
    long long total_threads = (long long)E * 32;
    int blocks = (int)((total_threads + 255) / 256);
    scatter_kernel<<<blocks, 256>>>(feature, src, dst, w, E);

    // 3) GEMM + bias + relu
    gemm_bias_relu_kernel<<<(M + 127) / 128, 256>>>(Wm, bias, out, M);
}

// round 4
// speedup vs baseline: 1.4555x; 1.4555x over previous
#include <cuda_runtime.h>

#define D 128
#define MAX_NODES 50048
#define MAX_E     1048576

// Scratch (allocation-free rule: __device__ globals)
__device__ float g_agg[MAX_NODES * D];
__device__ int   g_count[MAX_NODES];
__device__ int   g_start[MAX_NODES + 1];
__device__ int   g_cursor[MAX_NODES];
__device__ int   g_eid[MAX_E];

// ---------------------------------------------------------------------------
// 1) zero per-node edge counts
// ---------------------------------------------------------------------------
__global__ void zero_count_kernel(int N) {
    int i = blockIdx.x * blockDim.x + threadIdx.x;
    if (i < N) g_count[i] = 0;
}

// ---------------------------------------------------------------------------
// 2) histogram of dst
// ---------------------------------------------------------------------------
__global__ void hist_kernel(const int* __restrict__ dst, int E) {
    int e = blockIdx.x * blockDim.x + threadIdx.x;
    if (e < E) atomicAdd(&g_count[dst[e]], 1);
}

// ---------------------------------------------------------------------------
// 3) exclusive prefix scan over g_count (single block, 1024 threads)
//    writes g_start[0..N] and g_cursor[0..N-1]
// ---------------------------------------------------------------------------
__global__ void scan_kernel(int N) {
    __shared__ int part[1024];
    int t = threadIdx.x;
    int chunk = (N + 1023) >> 10;
    int lo = t * chunk;
    int hi = lo + chunk; if (hi > N) hi = N;
    if (lo > N) lo = N;

    int s = 0;
    for (int i = lo; i < hi; i++) s += g_count[i];
    part[t] = s;
    __syncthreads();

    // Hillis-Steele inclusive scan over 1024 partials
    for (int off = 1; off < 1024; off <<= 1) {
        int v = part[t];
        int u = (t >= off) ? part[t - off] : 0;
        __syncthreads();
        part[t] = v + u;
        __syncthreads();
    }

    int run = (t == 0) ? 0 : part[t - 1];   // exclusive offset for this chunk
    for (int i = lo; i < hi; i++) {
        int c = g_count[i];
        g_start[i]  = run;
        g_cursor[i] = run;
        run += c;
    }
    if (t == 1023) g_start[N] = part[1023];   // total
}

// ---------------------------------------------------------------------------
// 4) permute: bucket edge ids by dst
// ---------------------------------------------------------------------------
__global__ void permute_kernel(const int* __restrict__ dst, int E) {
    int e = blockIdx.x * blockDim.x + threadIdx.x;
    if (e < E) {
        int pos = atomicAdd(&g_cursor[dst[e]], 1);
        g_eid[pos] = e;
    }
}

// ---------------------------------------------------------------------------
// 5) gather-aggregate: one warp per node, register accumulation, single store.
//    No float atomics, no zero-fill of g_agg needed.
// ---------------------------------------------------------------------------
__global__ void aggregate_kernel(const float* __restrict__ feature,
                                 const int* __restrict__ src,
                                 const float* __restrict__ w,
                                 int N) {
    int t = blockIdx.x * blockDim.x + threadIdx.x;
    int n = t >> 5;
    if (n >= N) return;
    int lane = t & 31;

    int beg = g_start[n];
    int end = g_start[n + 1];

    float4 acc = make_float4(0.f, 0.f, 0.f, 0.f);
    for (int i = beg; i < end; i++) {
        int   e  = __ldg(&g_eid[i]);       // converged: one transaction, broadcast
        int   s  = __ldg(&src[e]);
        float we = __ldg(&w[e]);
        float4 v = *(const float4*)(feature + (size_t)s * D + lane * 4);
        acc.x += v.x * we;
        acc.y += v.y * we;
        acc.z += v.z * we;
        acc.w += v.w * we;
    }
    *(float4*)(g_agg + (size_t)n * D + lane * 4) = acc;
}

// ---------------------------------------------------------------------------
// 6) out = relu(agg @ W^T + b)  (unchanged fp32 tiled GEMM)
// ---------------------------------------------------------------------------
#define BK 32
#define SAP 132

__global__ void gemm_bias_relu_kernel(const float* __restrict__ Wm,
                                      const float* __restrict__ bias,
                                      float* __restrict__ out,
                                      int M) {
    __shared__ float sA[BK * SAP];
    __shared__ float sW[BK * SAP];

    int tid = threadIdx.x;
    int tx = tid & 15;
    int ty = tid >> 4;
    int br = blockIdx.x * 128;

    float acc[8][8];
#pragma unroll
    for (int i = 0; i < 8; i++)
#pragma unroll
        for (int j = 0; j < 8; j++) acc[i][j] = 0.f;

    for (int kt = 0; kt < D; kt += BK) {
#pragma unroll
        for (int it = 0; it < 4; it++) {
            int idx4 = tid + it * 256;
            int m  = idx4 >> 3;
            int kq = idx4 & 7;
            int k  = kq * 4;

            float4 va = make_float4(0.f, 0.f, 0.f, 0.f);
            if (br + m < M)
                va = *(const float4*)(g_agg + (size_t)(br + m) * D + kt + k);
            sA[(k + 0) * SAP + m] = va.x;
            sA[(k + 1) * SAP + m] = va.y;
            sA[(k + 2) * SAP + m] = va.z;
            sA[(k + 3) * SAP + m] = va.w;

            float4 vw = *(const float4*)(Wm + m * D + kt + k);
            sW[(k + 0) * SAP + m] = vw.x;
            sW[(k + 1) * SAP + m] = vw.y;
            sW[(k + 2) * SAP + m] = vw.z;
            sW[(k + 3) * SAP + m] = vw.w;
        }
        __syncthreads();

#pragma unroll
        for (int k = 0; k < BK; k++) {
            float a[8], wr[8];
            *(float4*)(a)      = *(const float4*)&sA[k * SAP + ty * 8];
            *(float4*)(a + 4)  = *(const float4*)&sA[k * SAP + ty * 8 + 4];
            *(float4*)(wr)     = *(const float4*)&sW[k * SAP + tx * 8];
            *(float4*)(wr + 4) = *(const float4*)&sW[k * SAP + tx * 8 + 4];
#pragma unroll
            for (int i = 0; i < 8; i++)
#pragma unroll
                for (int j = 0; j < 8; j++)
                    acc[i][j] += a[i] * wr[j];
        }
        __syncthreads();
    }

    float bv[8];
#pragma unroll
    for (int j = 0; j < 8; j++) bv[j] = bias[tx * 8 + j];

#pragma unroll
    for (int i = 0; i < 8; i++) {
        int m = br + ty * 8 + i;
        if (m < M) {
            float r[8];
#pragma unroll
            for (int j = 0; j < 8; j++) {
                float v = acc[i][j] + bv[j];
                r[j] = v > 0.f ? v : 0.f;
            }
            float* op = out + (size_t)m * D + tx * 8;
            *(float4*)(op)     = *(const float4*)(r);
            *(float4*)(op + 4) = *(const float4*)(r + 4);
        }
    }
}

// ---------------------------------------------------------------------------
// Launch
// Inputs: feature f32[N*128], src i32[E], dst i32[E], w f32[E],
//         W f32[128*128], b f32[128] ; output f32[N*128]
// ---------------------------------------------------------------------------
extern "C" void kernel_launch(void* const* d_in, const int* in_sizes, int n_in,
                              void* d_out, int out_size) {
    const float* feature = (const float*)d_in[0];
    const int*   src     = (const int*)d_in[1];
    const int*   dst     = (const int*)d_in[2];
    const float* w       = (const float*)d_in[3];
    const float* Wm      = (const float*)d_in[4];
    const float* bias    = (const float*)d_in[5];
    float*       out     = (float*)d_out;

    int M = in_sizes[0] / D;
    int E = in_sizes[1];
    if (E > MAX_E) E = MAX_E;

    zero_count_kernel<<<(M + 255) / 256, 256>>>(M);
    hist_kernel<<<(E + 255) / 256, 256>>>(dst, E);
    scan_kernel<<<1, 1024>>>(M);
    permute_kernel<<<(E + 255) / 256, 256>>>(dst, E);

    long long agg_threads = (long long)M * 32;
    aggregate_kernel<<<(int)((agg_threads + 255) / 256), 256>>>(feature, src, w, M);

    gemm_bias_relu_kernel<<<(M + 127) / 128, 256>>>(Wm, bias, out, M);
}